// round 14
// baseline (speedup 1.0000x reference)
#include <cuda_runtime.h>
#include <cuda_fp16.h>
#include <cstdint>

#define BB 4
#define NN 4096
#define FF 128
#define TILES 256          // 4096 / 16 j-tiles
#define TPW   128          // tiles per warp (2-way j-split)

// ---------------- scratch (no allocations allowed) ----------------
// Fragment-major Wh: per (b, j-tile) a 4KB block of 8 chunks x 32 lanes x 16B.
__device__ uint4  g_WhF[(size_t)BB * 256 * 256 + 768];   // pad (B prefetch overrun)
__device__ float  g_si[BB * NN];
__device__ float2 g_uv[BB * NN + 64];                    // {e^{sj}, e^{0.2 sj}}, padded

// ---------------- helpers ----------------
__device__ __forceinline__ unsigned long long pack2(float lo, float hi) {
    unsigned long long r; asm("mov.b64 %0, {%1, %2};" : "=l"(r) : "f"(lo), "f"(hi)); return r;
}
__device__ __forceinline__ unsigned long long bcast2(float v) {
    unsigned long long r; asm("mov.b64 %0, {%1, %1};" : "=l"(r) : "f"(v)); return r;
}
__device__ __forceinline__ void fma2(unsigned long long& d, unsigned long long a, unsigned long long b) {
    asm("fma.rn.f32x2 %0, %1, %2, %0;" : "+l"(d) : "l"(a), "l"(b));
}
__device__ __forceinline__ float2 unpack2(unsigned long long v) {
    float2 f; asm("mov.b64 {%0, %1}, %2;" : "=f"(f.x), "=f"(f.y) : "l"(v)); return f;
}
__device__ __forceinline__ uint32_t pkhf2(float lo, float hi) {
    uint32_t r;
    asm("{ .reg .f16 l, h; cvt.rn.f16.f32 l, %1; cvt.rn.f16.f32 h, %2; mov.b32 %0, {l, h}; }"
        : "=r"(r) : "f"(lo), "f"(hi));
    return r;
}
__device__ __forceinline__ float2 uphf2(uint32_t v) {
    float2 f;
    asm("{ .reg .f16 l, h; mov.b32 {l, h}, %2; cvt.f32.f16 %0, l; cvt.f32.f16 %1, h; }"
        : "=f"(f.x), "=f"(f.y) : "r"(v));
    return f;
}
__device__ __forceinline__ void mma_fp16(float* c, uint32_t a0, uint32_t a1,
                                         uint32_t a2, uint32_t a3,
                                         uint32_t b0, uint32_t b1) {
    asm volatile(
        "mma.sync.aligned.m16n8k16.row.col.f32.f16.f16.f32 "
        "{%0,%1,%2,%3}, {%4,%5,%6,%7}, {%8,%9}, {%0,%1,%2,%3};"
        : "+f"(c[0]), "+f"(c[1]), "+f"(c[2]), "+f"(c[3])
        : "r"(a0), "r"(a1), "r"(a2), "r"(a3), "r"(b0), "r"(b1));
}

// =====================================================================
// Kernel A: Wh = h @ W ; 32 rows x 128 f per CTA, 256 threads.
// Epilogue: fp16 fragment-major store + si/sj/uv from fp32 accumulators.
// =====================================================================
__global__ void __launch_bounds__(256) k_wh(const float* __restrict__ h,
                                            const float* __restrict__ W,
                                            const float* __restrict__ a) {
    const int b = blockIdx.y;
    const int i0 = blockIdx.x * 32;

    __shared__ float hsT[32][40];
    __shared__ float Ws[32][128];
    __shared__ float aS[256];

    const int tid = threadIdx.x;
    aS[tid] = a[tid];
    const int fgrp = tid & 31, rgrp = tid >> 5;
    const int rbase = rgrp * 4, fbase = fgrp * 4;

    unsigned long long acc[4][2];
#pragma unroll
    for (int r = 0; r < 4; r++) { acc[r][0] = 0ULL; acc[r][1] = 0ULL; }

    for (int k0 = 0; k0 < FF; k0 += 32) {
        __syncthreads();
        {
            int r = tid >> 3, kq = tid & 7;
            float4 v = *(const float4*)(h + ((size_t)(b * NN + i0 + r)) * FF + k0 + kq * 4);
            hsT[kq * 4 + 0][r] = v.x;
            hsT[kq * 4 + 1][r] = v.y;
            hsT[kq * 4 + 2][r] = v.z;
            hsT[kq * 4 + 3][r] = v.w;
        }
#pragma unroll
        for (int q = 0; q < 4; q++) {
            int idx = tid + 256 * q;
            int kk = idx >> 5, fq = idx & 31;
            *(float4*)&Ws[kk][fq * 4] = *(const float4*)(W + (size_t)(k0 + kk) * FF + fq * 4);
        }
        __syncthreads();

#pragma unroll 8
        for (int kk = 0; kk < 32; kk++) {
            float4 hr = *(float4*)&hsT[kk][rbase];
            float4 wf = *(float4*)&Ws[kk][fbase];
            unsigned long long w01 = pack2(wf.x, wf.y);
            unsigned long long w23 = pack2(wf.z, wf.w);
            float hv[4] = {hr.x, hr.y, hr.z, hr.w};
#pragma unroll
            for (int r = 0; r < 4; r++) {
                unsigned long long hb = bcast2(hv[r]);
                fma2(acc[r][0], hb, w01);
                fma2(acc[r][1], hb, w23);
            }
        }
    }

    float va[4][4];
#pragma unroll
    for (int r = 0; r < 4; r++) {
        float2 t0 = unpack2(acc[r][0]);
        float2 t1 = unpack2(acc[r][1]);
        va[r][0] = t0.x; va[r][1] = t0.y; va[r][2] = t1.x; va[r][3] = t1.y;
    }

    // ---- fragment-major fp16 store ----
    {
        const int jg   = i0 + rbase;
        const int jt   = jg >> 4;
        const int jloc = jg & 15;
        const int c_   = (jloc >> 1) & 3;
        const int hi   = (jloc >> 3) & 1;
        uint32_t* tbase = (uint32_t*)g_WhF + (((size_t)(b * 256 + jt)) << 10);
#pragma unroll
        for (int f = 0; f < 4; f++) {
            const int fg = fbase + f;
            uint32_t u01 = pkhf2(va[0][f], va[1][f]);
            uint32_t u23 = pkhf2(va[2][f], va[3][f]);
            const int p  = fg >> 4;
            const int q  = ((fg >> 3) & 1) * 2 + hi;
            const int l0 = (fg & 7) * 4 + c_;
            tbase[p * 128 + l0 * 4 + q]       = u01;
            tbase[p * 128 + (l0 + 1) * 4 + q] = u23;
        }
    }

    // si/sj from fp32 accumulators
    float psi[4], psj[4];
#pragma unroll
    for (int r = 0; r < 4; r++) {
        float si = 0.f, sj = 0.f;
#pragma unroll
        for (int f = 0; f < 4; f++) {
            si += va[r][f] * aS[fbase + f];
            sj += va[r][f] * aS[FF + fbase + f];
        }
#pragma unroll
        for (int o = 16; o; o >>= 1) {
            si += __shfl_xor_sync(0xFFFFFFFFu, si, o);
            sj += __shfl_xor_sync(0xFFFFFFFFu, sj, o);
        }
        psi[r] = si; psj[r] = sj;
    }
    if (fgrp == 0) {
#pragma unroll
        for (int r = 0; r < 4; r++) {
            int row = b * NN + i0 + rbase + r;
            g_si[row] = psi[r];
            g_uv[row] = make_float2(__expf(psj[r]), __expf(0.2f * psj[r]));
        }
    }
}

// =====================================================================
// Kernel C: 64-thread CTA (2 warps), 16 rows; 2-way j-split across warps.
// Barrier-free main loop; B and adj register-pipelined 2 TILES DEEP
// (even/odd buffer sets), uv 1-deep (L1-resident). Smem reduce epilogue.
// =====================================================================
__global__ void __launch_bounds__(64, 5) k_attn(const int* __restrict__ adj,
                                                float* __restrict__ out) {
    __shared__ float sAcc[2][16][132];
    __shared__ float sZ[2][16];

    const int tid = threadIdx.x;
    const int lane = tid & 31, ww = tid >> 5;
    const int c = lane & 3, fq = lane >> 2;
    const int b = blockIdx.y;
    const int i0 = blockIdx.x * 16;

    const int r0 = i0 + fq;
    const int r1 = r0 + 8;
    const float si0 = g_si[b * NN + r0];
    const float si1 = g_si[b * NN + r1];
    const float c10 = __expf(si0), c20 = __expf(0.2f * si0), th0 = __expf(-si0);
    const float c11 = __expf(si1), c21 = __expf(0.2f * si1), th1 = __expf(-si1);

    const int2* a00 = (const int2*)(adj + ((size_t)(b * NN + r0)) * NN + 2 * c);
    const int2* a10 = (const int2*)(adj + ((size_t)(b * NN + r1)) * NN + 2 * c);
    const float4* uvp = (const float4*)(g_uv + (size_t)b * NN) + c;
    const uint4* bp = g_WhF + (((size_t)b) << 16) + lane;

    const int tBeg = ww * TPW;
    const int tEnd = tBeg + TPW;

    float acc[16][4];
#pragma unroll
    for (int nt = 0; nt < 16; nt++)
#pragma unroll
        for (int k = 0; k < 4; k++) acc[nt][k] = 0.f;
    float z0 = 0.f, z1 = 0.f;

    // ---- prologue: B/adj for tiles tBeg (set0) and tBeg+1 (set1); uv tile tBeg ----
    uint4 B0[8], B1[8];
#pragma unroll
    for (int p = 0; p < 8; p++) {
        B0[p] = bp[(size_t)tBeg * 256 + p * 32];
        B1[p] = bp[(size_t)(tBeg + 1) * 256 + p * 32];
    }
    float4 Ua = uvp[tBeg * 8], Ub = uvp[tBeg * 8 + 4];
    int2 A00_0 = __ldcs(a00 + tBeg * 8),       A01_0 = __ldcs(a00 + tBeg * 8 + 4);
    int2 A10_0 = __ldcs(a10 + tBeg * 8),       A11_0 = __ldcs(a10 + tBeg * 8 + 4);
    int2 A00_1 = __ldcs(a00 + tBeg * 8 + 8),   A01_1 = __ldcs(a00 + tBeg * 8 + 12);
    int2 A10_1 = __ldcs(a10 + tBeg * 8 + 8),   A11_1 = __ldcs(a10 + tBeg * 8 + 12);

    auto step = [&](int tc, uint4* B, int2& A00, int2& A01, int2& A10, int2& A11) {
        // ---- P for tile tc ----
        float p00 = A00.x > 0 ? (Ua.x > th0 ? c10 * Ua.x : c20 * Ua.y) : 0.f;
        float p01 = A00.y > 0 ? (Ua.z > th0 ? c10 * Ua.z : c20 * Ua.w) : 0.f;
        float p08 = A01.x > 0 ? (Ub.x > th0 ? c10 * Ub.x : c20 * Ub.y) : 0.f;
        float p09 = A01.y > 0 ? (Ub.z > th0 ? c10 * Ub.z : c20 * Ub.w) : 0.f;
        float p10 = A10.x > 0 ? (Ua.x > th1 ? c11 * Ua.x : c21 * Ua.y) : 0.f;
        float p11 = A10.y > 0 ? (Ua.z > th1 ? c11 * Ua.z : c21 * Ua.w) : 0.f;
        float p18 = A11.x > 0 ? (Ub.x > th1 ? c11 * Ub.x : c21 * Ub.y) : 0.f;
        float p19 = A11.y > 0 ? (Ub.z > th1 ? c11 * Ub.z : c21 * Ub.w) : 0.f;

        // uv for tile tc+1 (1-deep, L1; padded, unguarded)
        Ua = uvp[(tc + 1) * 8];
        Ub = uvp[(tc + 1) * 8 + 4];
        // adj refill for tile tc+2 (2-deep, guarded)
        if (tc + 2 < tEnd) {
            int o = (tc + 2) * 8;
            A00 = __ldcs(a00 + o); A01 = __ldcs(a00 + o + 4);
            A10 = __ldcs(a10 + o); A11 = __ldcs(a10 + o + 4);
        }

        // fp16 quantize; Z from quantized values
        uint32_t ah0 = pkhf2(p00, p01), ah1 = pkhf2(p10, p11);
        uint32_t ah2 = pkhf2(p08, p09), ah3 = pkhf2(p18, p19);
        float2 q0 = uphf2(ah0), q1 = uphf2(ah1), q2 = uphf2(ah2), q3 = uphf2(ah3);
        z0 += (q0.x + q0.y) + (q2.x + q2.y);
        z1 += (q1.x + q1.y) + (q3.x + q3.y);

        // mma from registers; roll B[p] to tile tc+2 (padded, unguarded)
        const uint4* bt = bp + (size_t)(tc + 2) * 256;
#pragma unroll
        for (int p = 0; p < 8; p++) {
            uint4 bv = B[p];
            mma_fp16(acc[2 * p],     ah0, ah1, ah2, ah3, bv.x, bv.y);
            mma_fp16(acc[2 * p + 1], ah0, ah1, ah2, ah3, bv.z, bv.w);
            B[p] = bt[p * 32];
        }
    };

#pragma unroll 1
    for (int t = tBeg; t < tEnd; t += 2) {
        step(t,     B0, A00_0, A01_0, A10_0, A11_0);
        step(t + 1, B1, A00_1, A01_1, A10_1, A11_1);
    }

    // ---- per-warp Z reduction over the 4 lanes sharing a row ----
    z0 += __shfl_xor_sync(0xFFFFFFFFu, z0, 1);
    z0 += __shfl_xor_sync(0xFFFFFFFFu, z0, 2);
    z1 += __shfl_xor_sync(0xFFFFFFFFu, z1, 1);
    z1 += __shfl_xor_sync(0xFFFFFFFFu, z1, 2);
    if (c == 0) { sZ[ww][fq] = z0; sZ[ww][fq + 8] = z1; }

    // ---- dump accumulators to smem ----
#pragma unroll
    for (int nt = 0; nt < 16; nt++) {
        *(float2*)&sAcc[ww][fq][nt * 8 + 2 * c]     = make_float2(acc[nt][0], acc[nt][1]);
        *(float2*)&sAcc[ww][fq + 8][nt * 8 + 2 * c] = make_float2(acc[nt][2], acc[nt][3]);
    }
    __syncthreads();

    // ---- reduce + normalize + ELU + store (64 threads x 32 outputs) ----
    const int r = tid >> 2;
    const int cb = (tid & 3) * 32;
    const float iz = 1.0f / (sZ[0][r] + sZ[1][r]);
    float* op = out + ((size_t)(b * NN + i0 + r)) * FF + cb;
#pragma unroll
    for (int k = 0; k < 8; k++) {
        float4 v0 = *(const float4*)&sAcc[0][r][cb + 4 * k];
        float4 v1 = *(const float4*)&sAcc[1][r][cb + 4 * k];
        float4 v;
        float x;
        x = (v0.x + v1.x) * iz; v.x = x > 0.f ? x : (__expf(x) - 1.0f);
        x = (v0.y + v1.y) * iz; v.y = x > 0.f ? x : (__expf(x) - 1.0f);
        x = (v0.z + v1.z) * iz; v.z = x > 0.f ? x : (__expf(x) - 1.0f);
        x = (v0.w + v1.w) * iz; v.w = x > 0.f ? x : (__expf(x) - 1.0f);
        *(float4*)(op + 4 * k) = v;
    }
}

// =====================================================================
extern "C" void kernel_launch(void* const* d_in, const int* in_sizes, int n_in,
                              void* d_out, int out_size) {
    const float* h   = (const float*)d_in[0];
    const int*   adj = (const int*)d_in[1];
    const float* W   = (const float*)d_in[2];
    const float* a   = (const float*)d_in[3];
    float* out = (float*)d_out;

    k_wh<<<dim3(NN / 32, BB), 256>>>(h, W, a);
    k_attn<<<dim3(NN / 16, BB), 64>>>(adj, out);
}

// round 15
// speedup vs baseline: 1.7549x; 1.7549x over previous
#include <cuda_runtime.h>
#include <cuda_fp16.h>
#include <cstdint>

#define BB 4
#define NN 4096
#define FF 128
#define TILES 256          // 4096 / 16 j-tiles
#define TPW   128          // tiles per warp (2-way j-split)

// ---------------- scratch (no allocations allowed) ----------------
// Fragment-major Wh: per (b, j-tile) a 4KB block of 8 chunks x 32 lanes x 16B.
__device__ uint4  g_WhF[(size_t)BB * 256 * 256 + 512];   // pad (B prefetch overrun)
__device__ float  g_si[BB * NN];
__device__ float2 g_uv[BB * NN + 64];                    // {e^{sj}, e^{0.2 sj}}, padded

// ---------------- helpers ----------------
__device__ __forceinline__ unsigned long long pack2(float lo, float hi) {
    unsigned long long r; asm("mov.b64 %0, {%1, %2};" : "=l"(r) : "f"(lo), "f"(hi)); return r;
}
__device__ __forceinline__ unsigned long long bcast2(float v) {
    unsigned long long r; asm("mov.b64 %0, {%1, %1};" : "=l"(r) : "f"(v)); return r;
}
__device__ __forceinline__ void fma2(unsigned long long& d, unsigned long long a, unsigned long long b) {
    asm("fma.rn.f32x2 %0, %1, %2, %0;" : "+l"(d) : "l"(a), "l"(b));
}
__device__ __forceinline__ float2 unpack2(unsigned long long v) {
    float2 f; asm("mov.b64 {%0, %1}, %2;" : "=f"(f.x), "=f"(f.y) : "l"(v)); return f;
}
// pack two floats -> fp16x2 in ONE packed cvt (first arg low half)
__device__ __forceinline__ uint32_t pkhf2(float lo, float hi) {
    uint32_t r;
    asm("cvt.rn.f16x2.f32 %0, %2, %1;" : "=r"(r) : "f"(lo), "f"(hi));
    return r;
}
__device__ __forceinline__ void mma_fp16(float* c, uint32_t a0, uint32_t a1,
                                         uint32_t a2, uint32_t a3,
                                         uint32_t b0, uint32_t b1) {
    asm volatile(
        "mma.sync.aligned.m16n8k16.row.col.f32.f16.f16.f32 "
        "{%0,%1,%2,%3}, {%4,%5,%6,%7}, {%8,%9}, {%0,%1,%2,%3};"
        : "+f"(c[0]), "+f"(c[1]), "+f"(c[2]), "+f"(c[3])
        : "r"(a0), "r"(a1), "r"(a2), "r"(a3), "r"(b0), "r"(b1));
}

// =====================================================================
// Kernel A: Wh = h @ W ; 32 rows x 128 f per CTA, 256 threads.
// Epilogue: fp16 fragment-major store + si/sj/uv from fp32 accumulators.
// =====================================================================
__global__ void __launch_bounds__(256) k_wh(const float* __restrict__ h,
                                            const float* __restrict__ W,
                                            const float* __restrict__ a) {
    const int b = blockIdx.y;
    const int i0 = blockIdx.x * 32;

    __shared__ float hsT[32][40];
    __shared__ float Ws[32][128];
    __shared__ float aS[256];

    const int tid = threadIdx.x;
    aS[tid] = a[tid];
    const int fgrp = tid & 31, rgrp = tid >> 5;
    const int rbase = rgrp * 4, fbase = fgrp * 4;

    unsigned long long acc[4][2];
#pragma unroll
    for (int r = 0; r < 4; r++) { acc[r][0] = 0ULL; acc[r][1] = 0ULL; }

    for (int k0 = 0; k0 < FF; k0 += 32) {
        __syncthreads();
        {
            int r = tid >> 3, kq = tid & 7;
            float4 v = *(const float4*)(h + ((size_t)(b * NN + i0 + r)) * FF + k0 + kq * 4);
            hsT[kq * 4 + 0][r] = v.x;
            hsT[kq * 4 + 1][r] = v.y;
            hsT[kq * 4 + 2][r] = v.z;
            hsT[kq * 4 + 3][r] = v.w;
        }
#pragma unroll
        for (int q = 0; q < 4; q++) {
            int idx = tid + 256 * q;
            int kk = idx >> 5, fq = idx & 31;
            *(float4*)&Ws[kk][fq * 4] = *(const float4*)(W + (size_t)(k0 + kk) * FF + fq * 4);
        }
        __syncthreads();

#pragma unroll 8
        for (int kk = 0; kk < 32; kk++) {
            float4 hr = *(float4*)&hsT[kk][rbase];
            float4 wf = *(float4*)&Ws[kk][fbase];
            unsigned long long w01 = pack2(wf.x, wf.y);
            unsigned long long w23 = pack2(wf.z, wf.w);
            float hv[4] = {hr.x, hr.y, hr.z, hr.w};
#pragma unroll
            for (int r = 0; r < 4; r++) {
                unsigned long long hb = bcast2(hv[r]);
                fma2(acc[r][0], hb, w01);
                fma2(acc[r][1], hb, w23);
            }
        }
    }

    float va[4][4];
#pragma unroll
    for (int r = 0; r < 4; r++) {
        float2 t0 = unpack2(acc[r][0]);
        float2 t1 = unpack2(acc[r][1]);
        va[r][0] = t0.x; va[r][1] = t0.y; va[r][2] = t1.x; va[r][3] = t1.y;
    }

    // ---- fragment-major fp16 store ----
    {
        const int jg   = i0 + rbase;
        const int jt   = jg >> 4;
        const int jloc = jg & 15;
        const int c_   = (jloc >> 1) & 3;
        const int hi   = (jloc >> 3) & 1;
        uint32_t* tbase = (uint32_t*)g_WhF + (((size_t)(b * 256 + jt)) << 10);
#pragma unroll
        for (int f = 0; f < 4; f++) {
            const int fg = fbase + f;
            uint32_t u01 = pkhf2(va[0][f], va[1][f]);
            uint32_t u23 = pkhf2(va[2][f], va[3][f]);
            const int p  = fg >> 4;
            const int q  = ((fg >> 3) & 1) * 2 + hi;
            const int l0 = (fg & 7) * 4 + c_;
            tbase[p * 128 + l0 * 4 + q]       = u01;
            tbase[p * 128 + (l0 + 1) * 4 + q] = u23;
        }
    }

    // si/sj from fp32 accumulators
    float psi[4], psj[4];
#pragma unroll
    for (int r = 0; r < 4; r++) {
        float si = 0.f, sj = 0.f;
#pragma unroll
        for (int f = 0; f < 4; f++) {
            si += va[r][f] * aS[fbase + f];
            sj += va[r][f] * aS[FF + fbase + f];
        }
#pragma unroll
        for (int o = 16; o; o >>= 1) {
            si += __shfl_xor_sync(0xFFFFFFFFu, si, o);
            sj += __shfl_xor_sync(0xFFFFFFFFu, sj, o);
        }
        psi[r] = si; psj[r] = sj;
    }
    if (fgrp == 0) {
#pragma unroll
        for (int r = 0; r < 4; r++) {
            int row = b * NN + i0 + rbase + r;
            g_si[row] = psi[r];
            g_uv[row] = make_float2(__expf(psj[r]), __expf(0.2f * psj[r]));
        }
    }
}

// =====================================================================
// Kernel C: 64-thread CTA (2 warps), 16 rows; 2-way j-split across warps.
// Barrier-free main loop; B register-rolled 1 tile deep (R13 proven).
// genP via exp(lrelu(x+y)) = max(e^x u, e^0.2x v): no threshold compare.
// Quantize with one packed cvt; Z from unquantized p (no round-trip).
// =====================================================================
__global__ void __launch_bounds__(64, 6) k_attn(const int* __restrict__ adj,
                                                float* __restrict__ out) {
    __shared__ float sAcc[2][16][132];
    __shared__ float sZ[2][16];

    const int tid = threadIdx.x;
    const int lane = tid & 31, ww = tid >> 5;
    const int c = lane & 3, fq = lane >> 2;
    const int b = blockIdx.y;
    const int i0 = blockIdx.x * 16;

    const int r0 = i0 + fq;
    const int r1 = r0 + 8;
    const float si0 = g_si[b * NN + r0];
    const float si1 = g_si[b * NN + r1];
    const float c10 = __expf(si0), c20 = __expf(0.2f * si0);
    const float c11 = __expf(si1), c21 = __expf(0.2f * si1);

    const int2* a00 = (const int2*)(adj + ((size_t)(b * NN + r0)) * NN + 2 * c);
    const int2* a10 = (const int2*)(adj + ((size_t)(b * NN + r1)) * NN + 2 * c);
    const float4* uvp = (const float4*)(g_uv + (size_t)b * NN) + c;
    const uint4* bp = g_WhF + (((size_t)b) << 16) + lane;

    const int tBeg = ww * TPW;
    const int tEnd = tBeg + TPW;

    float acc[16][4];
#pragma unroll
    for (int nt = 0; nt < 16; nt++)
#pragma unroll
        for (int k = 0; k < 4; k++) acc[nt][k] = 0.f;
    float z0 = 0.f, z1 = 0.f;

    // ---- prologue: tile tBeg ----
    uint4 B[8];
#pragma unroll
    for (int p = 0; p < 8; p++) B[p] = bp[(size_t)tBeg * 256 + p * 32];
    float4 Ua = uvp[tBeg * 8], Ub = uvp[tBeg * 8 + 4];
    int2 A00 = __ldcs(a00 + tBeg * 8), A01 = __ldcs(a00 + tBeg * 8 + 4);
    int2 A10 = __ldcs(a10 + tBeg * 8), A11 = __ldcs(a10 + tBeg * 8 + 4);

#pragma unroll 1
    for (int t = tBeg; t < tEnd; t++) {
        // ---- P for tile t: p = adj ? max(c1*u, c2*v) : 0 ----
        float p00 = A00.x > 0 ? fmaxf(c10 * Ua.x, c20 * Ua.y) : 0.f;
        float p01 = A00.y > 0 ? fmaxf(c10 * Ua.z, c20 * Ua.w) : 0.f;
        float p08 = A01.x > 0 ? fmaxf(c10 * Ub.x, c20 * Ub.y) : 0.f;
        float p09 = A01.y > 0 ? fmaxf(c10 * Ub.z, c20 * Ub.w) : 0.f;
        float p10 = A10.x > 0 ? fmaxf(c11 * Ua.x, c21 * Ua.y) : 0.f;
        float p11 = A10.y > 0 ? fmaxf(c11 * Ua.z, c21 * Ua.w) : 0.f;
        float p18 = A11.x > 0 ? fmaxf(c11 * Ub.x, c21 * Ub.y) : 0.f;
        float p19 = A11.y > 0 ? fmaxf(c11 * Ub.z, c21 * Ub.w) : 0.f;

        // refill uv (padded, unguarded) and adj (guarded) for tile t+1
        Ua = uvp[(t + 1) * 8];
        Ub = uvp[(t + 1) * 8 + 4];
        if (t + 1 < tEnd) {
            int o = (t + 1) * 8;
            A00 = __ldcs(a00 + o); A01 = __ldcs(a00 + o + 4);
            A10 = __ldcs(a10 + o); A11 = __ldcs(a10 + o + 4);
        }

        // Z from unquantized p (quantization noise averages out over 2048 terms)
        z0 += (p00 + p01) + (p08 + p09);
        z1 += (p10 + p11) + (p18 + p19);

        // fp16 quantize A fragments (single packed cvt each)
        uint32_t ah0 = pkhf2(p00, p01), ah1 = pkhf2(p10, p11);
        uint32_t ah2 = pkhf2(p08, p09), ah3 = pkhf2(p18, p19);

        // mma from registers; roll B[p] to tile t+1 (padded, unguarded)
        const uint4* bt = bp + (size_t)(t + 1) * 256;
#pragma unroll
        for (int p = 0; p < 8; p++) {
            uint4 bv = B[p];
            mma_fp16(acc[2 * p],     ah0, ah1, ah2, ah3, bv.x, bv.y);
            mma_fp16(acc[2 * p + 1], ah0, ah1, ah2, ah3, bv.z, bv.w);
            B[p] = bt[p * 32];
        }
    }

    // ---- per-warp Z reduction over the 4 lanes sharing a row ----
    z0 += __shfl_xor_sync(0xFFFFFFFFu, z0, 1);
    z0 += __shfl_xor_sync(0xFFFFFFFFu, z0, 2);
    z1 += __shfl_xor_sync(0xFFFFFFFFu, z1, 1);
    z1 += __shfl_xor_sync(0xFFFFFFFFu, z1, 2);
    if (c == 0) { sZ[ww][fq] = z0; sZ[ww][fq + 8] = z1; }

    // ---- dump accumulators to smem ----
#pragma unroll
    for (int nt = 0; nt < 16; nt++) {
        *(float2*)&sAcc[ww][fq][nt * 8 + 2 * c]     = make_float2(acc[nt][0], acc[nt][1]);
        *(float2*)&sAcc[ww][fq + 8][nt * 8 + 2 * c] = make_float2(acc[nt][2], acc[nt][3]);
    }
    __syncthreads();

    // ---- reduce + normalize + ELU + store (64 threads x 32 outputs) ----
    const int r = tid >> 2;
    const int cb = (tid & 3) * 32;
    const float iz = 1.0f / (sZ[0][r] + sZ[1][r]);
    float* op = out + ((size_t)(b * NN + i0 + r)) * FF + cb;
#pragma unroll
    for (int k = 0; k < 8; k++) {
        float4 v0 = *(const float4*)&sAcc[0][r][cb + 4 * k];
        float4 v1 = *(const float4*)&sAcc[1][r][cb + 4 * k];
        float4 v;
        float x;
        x = (v0.x + v1.x) * iz; v.x = x > 0.f ? x : (__expf(x) - 1.0f);
        x = (v0.y + v1.y) * iz; v.y = x > 0.f ? x : (__expf(x) - 1.0f);
        x = (v0.z + v1.z) * iz; v.z = x > 0.f ? x : (__expf(x) - 1.0f);
        x = (v0.w + v1.w) * iz; v.w = x > 0.f ? x : (__expf(x) - 1.0f);
        *(float4*)(op + 4 * k) = v;
    }
}

// =====================================================================
extern "C" void kernel_launch(void* const* d_in, const int* in_sizes, int n_in,
                              void* d_out, int out_size) {
    const float* h   = (const float*)d_in[0];
    const int*   adj = (const int*)d_in[1];
    const float* W   = (const float*)d_in[2];
    const float* a   = (const float*)d_in[3];
    float* out = (float*)d_out;

    k_wh<<<dim3(NN / 32, BB), 256>>>(h, W, a);
    k_attn<<<dim3(NN / 16, BB), 64>>>(adj, out);
}